// round 2
// baseline (speedup 1.0000x reference)
#include <cuda_runtime.h>
#include <float.h>

// ROI max pool, two-phase:
//  1) transpose features [2,256,50,50] -> channel-last scratch [2,50,50,256]
//  2) pool: block = (roi, 32-channel group); warp = one (i,j) bin across 32
//     consecutive channels -> uniform loop bounds per warp, coalesced loads.
//     Results staged in smem, written out coalesced (out is [n][c][i][j]).

#define OUTP 7
#define NBINS 49            // 7*7
#define CCH  256
#define HH   50
#define WW   50
#define HWSZ (HH * WW)      // 2500
#define BB   2

// channel-last scratch: [B][H*W][C] = 2*2500*256 floats = 10.24 MB
__device__ float g_feat_t[BB * HWSZ * CCH];

// ---------------- transpose: [b][c][hw] -> [b][hw][c], 32x32 smem tiles ----
__global__ void transpose_kernel(const float* __restrict__ feat)
{
    __shared__ float tile[32][33];
    int b   = blockIdx.z;
    int hw0 = blockIdx.x * 32;
    int c0  = blockIdx.y * 32;

    int hw_r = hw0 + threadIdx.x;
    #pragma unroll
    for (int r = threadIdx.y; r < 32; r += 8) {
        if (hw_r < HWSZ)
            tile[r][threadIdx.x] = feat[((size_t)b * CCH + c0 + r) * HWSZ + hw_r];
    }
    __syncthreads();
    #pragma unroll
    for (int r = threadIdx.y; r < 32; r += 8) {
        int hw_w = hw0 + r;
        if (hw_w < HWSZ)
            g_feat_t[((size_t)b * HWSZ + hw_w) * CCH + c0 + threadIdx.x] =
                tile[threadIdx.x][r];
    }
}

// ---------------- pooling ----------------
// grid: 128 rois * 8 channel-groups; block: 256 threads = 8 warps
__global__ void roi_pool_kernel(const float* __restrict__ rois,
                                float* __restrict__ out)
{
    __shared__ float s[NBINS][33];

    int n    = blockIdx.x >> 3;
    int cg   = blockIdx.x & 7;
    int lane = threadIdx.x & 31;
    int warp = threadIdx.x >> 5;

    const float* r = rois + n * 5;
    int im = (int)rintf(r[0]);
    int x1 = (int)rintf(r[1] * 0.0625f);
    int y1 = (int)rintf(r[2] * 0.0625f);
    int x2 = (int)rintf(r[3] * 0.0625f);
    int y2 = (int)rintf(r[4] * 0.0625f);
    int h  = y2 - y1 + 1;
    int w  = x2 - x1 + 1;

    // per-lane channel base in channel-last layout
    const float* base = g_feat_t + (size_t)im * HWSZ * CCH + cg * 32 + lane;

    for (int ij = warp; ij < NBINS; ij += 8) {
        int i = ij / OUTP;
        int j = ij - i * OUTP;

        int ys = i * h / OUTP + y1;
        int ye = ((i + 1) * h + OUTP - 1) / OUTP + y1;
        int xs = j * w / OUTP + x1;
        int xe = ((j + 1) * w + OUTP - 1) / OUTP + x1;
        ys = max(ys, 0);  xs = max(xs, 0);
        ye = min(ye, HH); xe = min(xe, WW);

        float acc = -FLT_MAX;
        for (int y = ys; y < ye; ++y) {
            const float* row = base + (size_t)(y * WW) * CCH;
            for (int x = xs; x < xe; ++x) {
                acc = fmaxf(acc, __ldg(row + (size_t)x * CCH));
            }
        }
        s[ij][lane] = acc;
    }
    __syncthreads();

    // out[n][c][ij]: block covers channels [cg*32, cg*32+32), all 49 bins.
    // Linear index idx = c_local*49 + ij -> consecutive threads write
    // consecutive out addresses (fully coalesced).
    float* outb = out + ((size_t)n * CCH + cg * 32) * NBINS;
    for (int idx = threadIdx.x; idx < 32 * NBINS; idx += 256) {
        int cl = idx / NBINS;
        int ij = idx - cl * NBINS;
        outb[idx] = s[ij][cl];
    }
}

extern "C" void kernel_launch(void* const* d_in, const int* in_sizes, int n_in,
                              void* d_out, int out_size)
{
    const float* feat = (const float*)d_in[0];
    const float* rois = (const float*)d_in[1];
    float* out = (float*)d_out;

    dim3 tgrid((HWSZ + 31) / 32, CCH / 32, BB);   // 79 x 8 x 2
    dim3 tblk(32, 8);
    transpose_kernel<<<tgrid, tblk>>>(feat);

    roi_pool_kernel<<<128 * 8, 256>>>(rois, out);
}

// round 3
// speedup vs baseline: 1.6875x; 1.6875x over previous
#include <cuda_runtime.h>
#include <float.h>

// ROI max pool, two-phase, high-parallelism:
//  1) transpose features [2,256,50,50] -> channel-last scratch [2,50,50,256]
//  2) pool: block = (roi, 32-ch group, i-row); 7 warps, warp = one (i,j) bin
//     across 32 consecutive channels -> uniform bounds per warp, coalesced
//     loads, ONE bin per warp (no serial chain). 50K warps total.

#define OUTP 7
#define NBINS 49
#define CCH  256
#define HH   50
#define WW   50
#define HWSZ (HH * WW)
#define BB   2

__device__ float g_feat_t[BB * HWSZ * CCH];   // [b][hw][c], 10.24 MB

// ---------------- transpose: [b][c][hw] -> [b][hw][c] ----------------
__global__ void transpose_kernel(const float* __restrict__ feat)
{
    __shared__ float tile[32][33];
    int b   = blockIdx.z;
    int hw0 = blockIdx.x * 32;
    int c0  = blockIdx.y * 32;

    int hw_r = hw0 + threadIdx.x;
    #pragma unroll
    for (int r = threadIdx.y; r < 32; r += 8) {
        if (hw_r < HWSZ)
            tile[r][threadIdx.x] = feat[((size_t)b * CCH + c0 + r) * HWSZ + hw_r];
    }
    __syncthreads();
    #pragma unroll
    for (int r = threadIdx.y; r < 32; r += 8) {
        int hw_w = hw0 + r;
        if (hw_w < HWSZ)
            g_feat_t[((size_t)b * HWSZ + hw_w) * CCH + c0 + threadIdx.x] =
                tile[threadIdx.x][r];
    }
}

// ---------------- pooling ----------------
// grid: 128*8*7 = 7168 blocks; block: 224 threads = 7 warps (one bin each)
__global__ __launch_bounds__(224) void roi_pool_kernel(
    const float* __restrict__ rois, float* __restrict__ out)
{
    __shared__ float s[OUTP][33];   // s[j][channel_local]

    int bi = blockIdx.x;
    int i  = bi % OUTP;
    int cg = (bi / OUTP) & 7;
    int n  = bi / (OUTP * 8);

    int lane = threadIdx.x & 31;
    int j    = threadIdx.x >> 5;    // warp id = bin column

    const float* r = rois + n * 5;
    int im = (int)rintf(r[0]);
    int x1 = (int)rintf(r[1] * 0.0625f);
    int y1 = (int)rintf(r[2] * 0.0625f);
    int x2 = (int)rintf(r[3] * 0.0625f);
    int y2 = (int)rintf(r[4] * 0.0625f);
    int h  = y2 - y1 + 1;
    int w  = x2 - x1 + 1;

    int ys = i * h / OUTP + y1;
    int ye = ((i + 1) * h + OUTP - 1) / OUTP + y1;
    int xs = j * w / OUTP + x1;
    int xe = ((j + 1) * w + OUTP - 1) / OUTP + x1;
    ys = max(ys, 0);  xs = max(xs, 0);
    ye = min(ye, HH); xe = min(xe, WW);

    const float* base = g_feat_t + (size_t)im * HWSZ * CCH + cg * 32 + lane;

    float acc = -FLT_MAX;
    for (int y = ys; y < ye; ++y) {
        const float* row = base + (size_t)(y * WW) * CCH;
        for (int x = xs; x < xe; ++x) {
            acc = fmaxf(acc, __ldg(row + (size_t)x * CCH));
        }
    }
    s[j][lane] = acc;
    __syncthreads();

    // Block owns out[n][cg*32+cl][i*7+j], cl in [0,32), j in [0,7):
    // 32 runs of 7 contiguous floats, stride 49 between runs.
    float* outb = out + ((size_t)n * CCH + cg * 32) * NBINS + i * OUTP;
    int idx = threadIdx.x;            // 0..223
    int cl  = idx / OUTP;
    int jj  = idx - cl * OUTP;
    outb[(size_t)cl * NBINS + jj] = s[jj][cl];
}

extern "C" void kernel_launch(void* const* d_in, const int* in_sizes, int n_in,
                              void* d_out, int out_size)
{
    const float* feat = (const float*)d_in[0];
    const float* rois = (const float*)d_in[1];
    float* out = (float*)d_out;

    dim3 tgrid((HWSZ + 31) / 32, CCH / 32, BB);
    dim3 tblk(32, 8);
    transpose_kernel<<<tgrid, tblk>>>(feat);

    roi_pool_kernel<<<128 * 8 * OUTP, 224>>>(rois, out);
}

// round 4
// speedup vs baseline: 2.4213x; 1.4349x over previous
#include <cuda_runtime.h>
#include <float.h>

// ROI max pool, two-phase, float4-vectorized over channels:
//  1) transpose features [2,256,50,50] -> channel-last scratch [2,50,50,256]
//  2) pool: block = (roi, 128-ch group, i-row); 7 warps (one j bin each);
//     each lane handles 4 consecutive channels via LDG.128 -> ~3x fewer
//     issued instructions than scalar version (issue-bound kernel).

#define OUTP 7
#define NBINS 49
#define CCH  256
#define HH   50
#define WW   50
#define HWSZ (HH * WW)
#define BB   2

__device__ __align__(16) float g_feat_t[BB * HWSZ * CCH];   // [b][hw][c]

// ---------------- transpose: [b][c][hw] -> [b][hw][c] ----------------
__global__ void transpose_kernel(const float* __restrict__ feat)
{
    __shared__ float tile[32][33];
    int b   = blockIdx.z;
    int hw0 = blockIdx.x * 32;
    int c0  = blockIdx.y * 32;

    int hw_r = hw0 + threadIdx.x;
    #pragma unroll
    for (int r = threadIdx.y; r < 32; r += 8) {
        if (hw_r < HWSZ)
            tile[r][threadIdx.x] = feat[((size_t)b * CCH + c0 + r) * HWSZ + hw_r];
    }
    __syncthreads();
    #pragma unroll
    for (int r = threadIdx.y; r < 32; r += 8) {
        int hw_w = hw0 + r;
        if (hw_w < HWSZ)
            g_feat_t[((size_t)b * HWSZ + hw_w) * CCH + c0 + threadIdx.x] =
                tile[threadIdx.x][r];
    }
}

// ---------------- pooling ----------------
// grid: 128 rois * 2 ch-groups * 7 i = 1792 blocks; 224 threads = 7 warps.
// warp j handles bin (i,j) for 128 channels (lane -> 4 channels, float4).
#define SPITCH 132
__global__ __launch_bounds__(224) void roi_pool_kernel(
    const float* __restrict__ rois, float* __restrict__ out)
{
    __shared__ float s[OUTP * SPITCH];   // s[j*SPITCH + c_local]

    int bi = blockIdx.x;
    int i  = bi % OUTP;
    int cg = (bi / OUTP) & 1;            // 0 or 1: channels [cg*128, +128)
    int n  = bi / (OUTP * 2);

    int lane = threadIdx.x & 31;
    int j    = threadIdx.x >> 5;         // warp id = bin column

    const float* r = rois + n * 5;
    int im = (int)rintf(r[0]);
    int x1 = (int)rintf(r[1] * 0.0625f);
    int y1 = (int)rintf(r[2] * 0.0625f);
    int x2 = (int)rintf(r[3] * 0.0625f);
    int y2 = (int)rintf(r[4] * 0.0625f);
    int h  = y2 - y1 + 1;
    int w  = x2 - x1 + 1;

    int ys = i * h / OUTP + y1;
    int ye = ((i + 1) * h + OUTP - 1) / OUTP + y1;
    int xs = j * w / OUTP + x1;
    int xe = ((j + 1) * w + OUTP - 1) / OUTP + x1;
    ys = max(ys, 0);  xs = max(xs, 0);
    ye = min(ye, HH); xe = min(xe, WW);

    // lane's 4-channel base in channel-last layout (16B aligned)
    const float4* base = (const float4*)
        (g_feat_t + (size_t)im * HWSZ * CCH + cg * 128 + lane * 4);

    float4 acc = make_float4(-FLT_MAX, -FLT_MAX, -FLT_MAX, -FLT_MAX);
    for (int y = ys; y < ye; ++y) {
        const float4* row = base + (size_t)(y * WW + xs) * (CCH / 4);
        for (int x = xs; x < xe; ++x) {
            float4 v = __ldg(row);
            acc.x = fmaxf(acc.x, v.x);
            acc.y = fmaxf(acc.y, v.y);
            acc.z = fmaxf(acc.z, v.z);
            acc.w = fmaxf(acc.w, v.w);
            row += CCH / 4;
        }
    }
    // conflict-free: lane stores 16B at s[j*SPITCH + 4*lane] (contiguous/warp)
    *(float4*)&s[j * SPITCH + lane * 4] = acc;
    __syncthreads();

    // Block owns out[n][cg*128 + c][i*7 + j], c in [0,128), j in [0,7):
    // 896 floats = 128 runs of 7 contiguous, 4 per thread, coalesced.
    float* outb = out + ((size_t)n * CCH + cg * 128) * NBINS + i * OUTP;
    #pragma unroll
    for (int idx = threadIdx.x; idx < 128 * OUTP; idx += 224) {
        int c  = idx / OUTP;
        int jj = idx - c * OUTP;
        outb[(size_t)c * NBINS + jj] = s[jj * SPITCH + c];
    }
}

extern "C" void kernel_launch(void* const* d_in, const int* in_sizes, int n_in,
                              void* d_out, int out_size)
{
    const float* feat = (const float*)d_in[0];
    const float* rois = (const float*)d_in[1];
    float* out = (float*)d_out;

    dim3 tgrid((HWSZ + 31) / 32, CCH / 32, BB);
    dim3 tblk(32, 8);
    transpose_kernel<<<tgrid, tblk>>>(feat);

    roi_pool_kernel<<<128 * 2 * OUTP, 224>>>(rois, out);
}